// round 8
// baseline (speedup 1.0000x reference)
#include <cuda_runtime.h>
#include <cuda_bf16.h>
#include <cstdint>

// ---------------------------------------------------------------------------
// label_loss: B=4.19M elements -> 3 scalars. Memory-bound (218 MB read).
// R8: bulk-copy double-buffered pipeline at 8 CTAs/SM (64 warps = 100% occ).
// Key insight from R5/R7: LDG version needs 40 regs (24 live loaded floats)
// capping occupancy at 48 warps; the SMEM-staged version's live set is small,
// so a 32-reg budget is feasible -> 64 warps. SMEM 27KB*8 = 216KB fits.
// Also hoisted per-tile pointer math (R7 alu=24.7%).
// R6 champion: 41.5us (LDG, DRAM 69%). R7: 43.7us (bulk@6CTA, DRAM 66%).
// ---------------------------------------------------------------------------

#define NBLK 1184       // 148 SMs * 8 CTAs -> one wave
#define NTHR 256
#define TILE 256        // elements per tile
#define LBYTES (TILE * 24)              // label/est bytes per tile (6144)
#define MBYTES (TILE * 4)               // mix bytes per tile (1024)
#define TXBYTES (2 * LBYTES + MBYTES)   // 13312

static __device__ float g_part[5][NBLK];
static __device__ int   g_count = 0;

__device__ __forceinline__ uint32_t s2u(const void* p) {
    uint32_t a;
    asm("{ .reg .u64 t; cvta.to.shared.u64 t, %1; cvt.u32.u64 %0, t; }"
        : "=r"(a) : "l"(p));
    return a;
}

__device__ __forceinline__ void mbar_init(uint32_t mb, uint32_t cnt) {
    asm volatile("mbarrier.init.shared.b64 [%0], %1;" :: "r"(mb), "r"(cnt) : "memory");
}

__device__ __forceinline__ void mbar_expect_tx(uint32_t mb, uint32_t bytes) {
    asm volatile("mbarrier.arrive.expect_tx.shared.b64 _, [%0], %1;"
                 :: "r"(mb), "r"(bytes) : "memory");
}

__device__ __forceinline__ void bulk_ld(uint32_t dst, const void* src,
                                        uint32_t bytes, uint32_t mb) {
    asm volatile(
        "cp.async.bulk.shared::cta.global.mbarrier::complete_tx::bytes "
        "[%0], [%1], %2, [%3];"
        :: "r"(dst), "l"(src), "r"(bytes), "r"(mb) : "memory");
}

__device__ __forceinline__ void mbar_wait(uint32_t mb, uint32_t phase) {
    uint32_t done = 0;
    while (!done) {
        asm volatile(
            "{\n\t.reg .pred p;\n\t"
            "mbarrier.try_wait.parity.acquire.cta.shared::cta.b64 p, [%1], %2, 0x989680;\n\t"
            "selp.b32 %0, 1, 0, p;\n\t}"
            : "=r"(done) : "r"(mb), "r"(phase) : "memory");
    }
}

__device__ __forceinline__ float angdiff_deg(float x1, float y1, float x2, float y2) {
    // |atan2(y1,x1) - atan2(y2,x2)| wrapped to [0, 180], in degrees.
    float cr = fmaf(y1, x2, -x1 * y2);
    float dt = fmaf(x1, x2,  y1 * y2);
    float p  = fabsf(cr);
    float q  = fabsf(dt);
    float mx = fmaxf(fmaxf(p, q), 1e-38f);
    float mn = fminf(p, q);
    float r  = __fdividef(mn, mx);       // r in [0, 1]
    float t2 = r * r;
    const float D = 57.29577951308232f;  // rad -> deg folded into coefficients
    float pl;
    pl = fmaf(t2, -0.01172120f * D,  0.05265332f * D);
    pl = fmaf(t2, pl,           -0.11643287f * D);
    pl = fmaf(t2, pl,            0.19354346f * D);
    pl = fmaf(t2, pl,           -0.33262347f * D);
    pl = fmaf(t2, pl,            0.99997726f * D);
    float at = r * pl;                   // atan(mn/mx) in degrees, [0, 45]
    float a  = (p > q)      ? (90.0f  - at) : at;
    a        = (dt < 0.0f)  ? (180.0f - a ) : a;
    return a;
}

struct Acc { float S, M, A1, A2; };

__device__ __forceinline__ void proc(
    float l00, float l01, float l10, float l11, float l20, float l21,
    float e0, float e1, float e2, float e3, float e4, float e5,
    int m, Acc& a)
{
    float d0 = e0 - l00, d1 = e1 - l10, d2 = e2 - l20;
    float s11 = fmaf(d2, d2, fmaf(d1, d1, d0 * d0));
    float f0 = e3 - l01, f1 = e4 - l11, f2 = e5 - l21;
    float s22 = fmaf(f2, f2, fmaf(f1, f1, f0 * f0));
    float g0 = e0 - l01, g1 = e1 - l11, g2 = e2 - l21;
    float s12 = fmaf(g2, g2, fmaf(g1, g1, g0 * g0));
    float h0 = e3 - l00, h1 = e4 - l10, h2 = e5 - l20;
    float s21 = fmaf(h2, h2, fmaf(h1, h1, h0 * h0));

    a.S += s11;
    float mixed = fminf(s11 + s22, s12 + s21);  // /3 deferred to finalize
    a.M  += (m != 0) ? mixed : 0.0f;

    float a11 = angdiff_deg(l00, l10, e0, e1);
    float a22 = angdiff_deg(l01, l11, e3, e4);
    float a12 = angdiff_deg(l00, l10, e3, e4);
    float a21 = angdiff_deg(l01, l11, e0, e1);
    bool ud = (a11 + a22) < (a12 + a21);
    a.A1 += ud ? a11 : a12;
    a.A2 += ud ? a22 : a21;
}

__global__ void __launch_bounds__(NTHR, 8)
fused_kernel(const float* __restrict__ label, const float* __restrict__ est,
             const int* __restrict__ mix, float* __restrict__ out, int B)
{
    __shared__ __align__(128) float sL[2][TILE * 6];
    __shared__ __align__(128) float sE[2][TILE * 6];
    __shared__ __align__(128) int   sM[2][TILE];
    __shared__ __align__(8) unsigned long long mbar[2];

    const int ntiles = B / TILE;
    const int tid = threadIdx.x;
    const int bid = blockIdx.x;

    const uint32_t mb0  = s2u(&mbar[0]), mb1  = s2u(&mbar[1]);
    const uint32_t sL0  = s2u(sL[0]),    sL1  = s2u(sL[1]);
    const uint32_t sE0  = s2u(sE[0]),    sE1  = s2u(sE[1]);
    const uint32_t sM0  = s2u(sM[0]),    sM1  = s2u(sM[1]);

    if (tid == 0) {
        mbar_init(mb0, 1);
        mbar_init(mb1, 1);
    }
    __syncthreads();

    // Prologue: issue tiles bid (buf0) and bid+NBLK (buf1).
    if (tid == 0) {
        if (bid < ntiles) {
            mbar_expect_tx(mb0, TXBYTES);
            bulk_ld(sL0, (const char*)label + (size_t)bid * LBYTES, LBYTES, mb0);
            bulk_ld(sE0, (const char*)est   + (size_t)bid * LBYTES, LBYTES, mb0);
            bulk_ld(sM0, (const char*)mix   + (size_t)bid * MBYTES, MBYTES, mb0);
        }
        if (bid + NBLK < ntiles) {
            mbar_expect_tx(mb1, TXBYTES);
            bulk_ld(sL1, (const char*)label + (size_t)(bid + NBLK) * LBYTES, LBYTES, mb1);
            bulk_ld(sE1, (const char*)est   + (size_t)(bid + NBLK) * LBYTES, LBYTES, mb1);
            bulk_ld(sM1, (const char*)mix   + (size_t)(bid + NBLK) * MBYTES, MBYTES, mb1);
        }
    }

    Acc a{0.f, 0.f, 0.f, 0.f};
    int c0 = 0;
    int ph0 = 0, ph1 = 0;
    int s = 0;

    // Pointers for the NEXT refill (tile g + 2*NBLK), advanced by constant
    // stride each iteration -- no per-tile 64-bit multiplies (R7 alu=24.7%).
    const char* Lr = (const char*)label + ((size_t)bid + 2 * NBLK) * LBYTES;
    const char* Er = (const char*)est   + ((size_t)bid + 2 * NBLK) * LBYTES;
    const char* Mr = (const char*)mix   + ((size_t)bid + 2 * NBLK) * MBYTES;

    for (int g = bid; g < ntiles; g += NBLK) {
        uint32_t mb = s ? mb1 : mb0;
        int& ph = s ? ph1 : ph0;
        mbar_wait(mb, ph);
        ph ^= 1;

        const float* Lp = (s ? sL[1] : sL[0]) + tid * 6;
        const float* Ep = (s ? sE[1] : sE[0]) + tid * 6;
        float2 La = *(const float2*)(Lp + 0);
        float2 Lb = *(const float2*)(Lp + 2);
        float2 Lc = *(const float2*)(Lp + 4);
        float2 Ea = *(const float2*)(Ep + 0);
        float2 Eb = *(const float2*)(Ep + 2);
        float2 Ec = *(const float2*)(Ep + 4);
        int m = (s ? sM[1] : sM[0])[tid];
        proc(La.x, La.y, Lb.x, Lb.y, Lc.x, Lc.y,
             Ea.x, Ea.y, Eb.x, Eb.y, Ec.x, Ec.y, m, a);
        c0 += (m == 0);

        __syncthreads();   // all threads done reading buf s -> safe to refill

        if (tid == 0 && g + 2 * NBLK < ntiles) {
            asm volatile("fence.proxy.async.shared::cta;" ::: "memory");
            mbar_expect_tx(mb, TXBYTES);
            bulk_ld(s ? sL1 : sL0, Lr, LBYTES, mb);
            bulk_ld(s ? sE1 : sE0, Er, LBYTES, mb);
            bulk_ld(s ? sM1 : sM0, Mr, MBYTES, mb);
        }
        Lr += (size_t)NBLK * LBYTES;
        Er += (size_t)NBLK * LBYTES;
        Mr += (size_t)NBLK * MBYTES;
        s ^= 1;
    }

    // Remainder elements (B % TILE != 0): direct loads by block 0.
    int rem = B - ntiles * TILE;
    if (rem && bid == 0 && tid < rem) {
        int i = ntiles * TILE + tid;
        const float* L = label + 6 * i;
        const float* E = est   + 6 * i;
        int m = mix[i];
        proc(L[0], L[1], L[2], L[3], L[4], L[5],
             E[0], E[1], E[2], E[3], E[4], E[5], m, a);
        c0 += (m == 0);
    }

    // Deterministic block reduction -> per-block float partials.
    float v[5] = {a.S, a.M, a.A1, a.A2, (float)c0};
    __shared__ float sh[5][NTHR / 32];
    #pragma unroll
    for (int k = 0; k < 5; k++) {
        float x = v[k];
        #pragma unroll
        for (int o = 16; o; o >>= 1) x += __shfl_down_sync(0xffffffffu, x, o);
        if ((tid & 31) == 0) sh[k][tid >> 5] = x;
    }
    __syncthreads();
    if (tid < 5) {
        float sm = 0.f;
        #pragma unroll
        for (int j = 0; j < NTHR / 32; j++) sm += sh[tid][j];
        g_part[tid][bid] = sm;
    }

    // ---- last-block-done finalize (deterministic fixed-order re-reduce) ----
    __shared__ int is_last;
    __threadfence();
    if (tid == 0) {
        int prev = atomicAdd(&g_count, 1);
        is_last = (prev == NBLK - 1);
    }
    __syncthreads();
    if (!is_last) return;
    __threadfence();

    float v5[5] = {0.f, 0.f, 0.f, 0.f, 0.f};
    for (int i = tid; i < NBLK; i += NTHR) {
        #pragma unroll
        for (int k = 0; k < 5; k++) v5[k] += g_part[k][i];
    }
    __shared__ float shf[5][NTHR / 32];
    #pragma unroll
    for (int k = 0; k < 5; k++) {
        float x = v5[k];
        #pragma unroll
        for (int o = 16; o; o >>= 1) x += __shfl_down_sync(0xffffffffu, x, o);
        if ((tid & 31) == 0) shf[k][tid >> 5] = x;
    }
    __syncthreads();
    if (tid == 0) {
        double t[5];
        #pragma unroll
        for (int k = 0; k < 5; k++) {
            float sm = 0.f;
            #pragma unroll
            for (int j = 0; j < NTHR / 32; j++) sm += shf[k][j];
            t[k] = (double)sm;
        }
        double Bn = (double)B;
        double single = t[0] / (3.0 * Bn);                   // S / (3B)
        out[0] = (float)((t[4] * single + t[1] / 3.0) / Bn); // label_loss
        out[1] = (float)(t[2] / Bn);                         // mae1
        out[2] = (float)(t[3] / Bn);                         // mae2
        g_count = 0;                     // reset for next graph replay
    }
}

extern "C" void kernel_launch(void* const* d_in, const int* in_sizes, int n_in,
                              void* d_out, int out_size)
{
    const float* label = (const float*)d_in[0];
    const float* est   = (const float*)d_in[1];
    const int*   mix   = (const int*)d_in[2];
    int B = in_sizes[2];  // mix_way element count

    fused_kernel<<<NBLK, NTHR>>>(label, est, mix, (float*)d_out, B);
}

// round 9
// speedup vs baseline: 1.0257x; 1.0257x over previous
#include <cuda_runtime.h>
#include <cuda_bf16.h>

// ---------------------------------------------------------------------------
// label_loss: B=4.19M elements -> 3 scalars. Memory-bound (218 MB read).
// R9: back to plain-LDG streaming (R6 design) but 1 element/thread with
// float2 loads. Live set: 12 loaded floats (vs 24 in the 2-elem float4 loop)
// -> fits the 32-reg/8-CTA operating point (64 warps/SM, reg file exactly
// full: 64*32*32 = 64K). Reg granularity is 8, so 32/64w or 40/48w are the
// only choices; R6 champion = 40/48w @ DRAM 69.4%, 41.5us. More warps =
// more outstanding LDGs = less exposed DRAM latency.
// R7/R8 bulk-copy pipeline abandoned: per-tile sync overhead (issue 68%).
// ---------------------------------------------------------------------------

#define NBLK 1184       // 148 SMs * 8 CTAs -> one wave
#define NTHR 256

static __device__ float g_part[5][NBLK];   // SoA: coalesced finalize reads
static __device__ int   g_count = 0;       // reset by the finalizing block

__device__ __forceinline__ float2 ldcs2(const float2* p) {
    float2 v;
    asm volatile("ld.global.cs.v2.f32 {%0,%1}, [%2];"
                 : "=f"(v.x), "=f"(v.y) : "l"(p));
    return v;
}

__device__ __forceinline__ int ldcsi(const int* p) {
    int v;
    asm volatile("ld.global.cs.s32 %0, [%1];" : "=r"(v) : "l"(p));
    return v;
}

__device__ __forceinline__ float angdiff_deg(float x1, float y1, float x2, float y2) {
    // |atan2(y1,x1) - atan2(y2,x2)| wrapped to [0, 180], in degrees.
    float cr = fmaf(y1, x2, -x1 * y2);
    float dt = fmaf(x1, x2,  y1 * y2);
    float p  = fabsf(cr);
    float q  = fabsf(dt);
    float mx = fmaxf(fmaxf(p, q), 1e-38f);
    float mn = fminf(p, q);
    float r  = __fdividef(mn, mx);       // r in [0, 1]
    float t2 = r * r;
    const float D = 57.29577951308232f;  // rad -> deg folded into coefficients
    float pl;
    pl = fmaf(t2, -0.01172120f * D,  0.05265332f * D);
    pl = fmaf(t2, pl,           -0.11643287f * D);
    pl = fmaf(t2, pl,            0.19354346f * D);
    pl = fmaf(t2, pl,           -0.33262347f * D);
    pl = fmaf(t2, pl,            0.99997726f * D);
    float at = r * pl;                   // atan(mn/mx) in degrees, [0, 45]
    float a  = (p > q)      ? (90.0f  - at) : at;
    a        = (dt < 0.0f)  ? (180.0f - a ) : a;
    return a;
}

struct Acc { float S, M, A1, A2; };

__device__ __forceinline__ void proc(
    float l00, float l01, float l10, float l11, float l20, float l21,
    float e0, float e1, float e2, float e3, float e4, float e5,
    int m, Acc& a)
{
    // l1 = (l00,l10,l20), l2 = (l01,l11,l21); e1 = (e0,e1,e2), e2 = (e3,e4,e5)
    float d0 = e0 - l00, d1 = e1 - l10, d2 = e2 - l20;
    float s11 = fmaf(d2, d2, fmaf(d1, d1, d0 * d0));
    float f0 = e3 - l01, f1 = e4 - l11, f2 = e5 - l21;
    float s22 = fmaf(f2, f2, fmaf(f1, f1, f0 * f0));
    float g0 = e0 - l01, g1 = e1 - l11, g2 = e2 - l21;
    float s12 = fmaf(g2, g2, fmaf(g1, g1, g0 * g0));
    float h0 = e3 - l00, h1 = e4 - l10, h2 = e5 - l20;
    float s21 = fmaf(h2, h2, fmaf(h1, h1, h0 * h0));

    a.S += s11;
    float mixed = fminf(s11 + s22, s12 + s21);  // /3 deferred to finalize
    a.M  += (m != 0) ? mixed : 0.0f;

    float a11 = angdiff_deg(l00, l10, e0, e1);
    float a22 = angdiff_deg(l01, l11, e3, e4);
    float a12 = angdiff_deg(l00, l10, e3, e4);
    float a21 = angdiff_deg(l01, l11, e0, e1);
    bool ud = (a11 + a22) < (a12 + a21);
    a.A1 += ud ? a11 : a12;
    a.A2 += ud ? a22 : a21;
}

__global__ void __launch_bounds__(NTHR, 8)
fused_kernel(const float* __restrict__ label, const float* __restrict__ est,
             const int* __restrict__ mix, float* __restrict__ out, int B)
{
    Acc a{0.f, 0.f, 0.f, 0.f};
    int c0 = 0;

    for (int i = blockIdx.x * NTHR + threadIdx.x; i < B; i += NBLK * NTHR) {
        const float2* Lp = (const float2*)(label + 6 * (size_t)i);
        const float2* Ep = (const float2*)(est   + 6 * (size_t)i);
        float2 La = ldcs2(Lp + 0);       // (l00, l01)
        float2 Lb = ldcs2(Lp + 1);       // (l10, l11)
        float2 Lc = ldcs2(Lp + 2);       // (l20, l21)
        float2 Ea = ldcs2(Ep + 0);       // (e0, e1)
        float2 Eb = ldcs2(Ep + 1);       // (e2, e3)
        float2 Ec = ldcs2(Ep + 2);       // (e4, e5)
        int m = ldcsi(mix + i);
        proc(La.x, La.y, Lb.x, Lb.y, Lc.x, Lc.y,
             Ea.x, Ea.y, Eb.x, Eb.y, Ec.x, Ec.y, m, a);
        c0 += (m == 0);
    }

    // Deterministic block reduction -> per-block float partials.
    float v[5] = {a.S, a.M, a.A1, a.A2, (float)c0};
    __shared__ float sh[5][NTHR / 32];
    #pragma unroll
    for (int k = 0; k < 5; k++) {
        float x = v[k];
        #pragma unroll
        for (int o = 16; o; o >>= 1) x += __shfl_down_sync(0xffffffffu, x, o);
        if ((threadIdx.x & 31) == 0) sh[k][threadIdx.x >> 5] = x;
    }
    __syncthreads();
    if (threadIdx.x < 5) {
        float s = 0.f;
        #pragma unroll
        for (int j = 0; j < NTHR / 32; j++) s += sh[threadIdx.x][j];
        g_part[threadIdx.x][blockIdx.x] = s;
    }

    // ---- last-block-done finalize (deterministic fixed-order re-reduce) ----
    __shared__ int is_last;
    __threadfence();                     // publish g_part before the count
    if (threadIdx.x == 0) {
        int prev = atomicAdd(&g_count, 1);
        is_last = (prev == NBLK - 1);
    }
    __syncthreads();
    if (!is_last) return;
    __threadfence();                     // acquire all blocks' g_part

    // Float accumulation (tree-structured; rel err ~1e-6, tol is 1e-3).
    float v5[5] = {0.f, 0.f, 0.f, 0.f, 0.f};
    for (int i = threadIdx.x; i < NBLK; i += NTHR) {
        #pragma unroll
        for (int k = 0; k < 5; k++) v5[k] += g_part[k][i];
    }
    __shared__ float shf[5][NTHR / 32];
    #pragma unroll
    for (int k = 0; k < 5; k++) {
        float x = v5[k];
        #pragma unroll
        for (int o = 16; o; o >>= 1) x += __shfl_down_sync(0xffffffffu, x, o);
        if ((threadIdx.x & 31) == 0) shf[k][threadIdx.x >> 5] = x;
    }
    __syncthreads();
    if (threadIdx.x == 0) {
        double t[5];
        #pragma unroll
        for (int k = 0; k < 5; k++) {
            float s = 0.f;
            #pragma unroll
            for (int j = 0; j < NTHR / 32; j++) s += shf[k][j];
            t[k] = (double)s;
        }
        double Bn = (double)B;
        double single = t[0] / (3.0 * Bn);                   // S / (3B)
        out[0] = (float)((t[4] * single + t[1] / 3.0) / Bn); // label_loss
        out[1] = (float)(t[2] / Bn);                         // mae1
        out[2] = (float)(t[3] / Bn);                         // mae2
        g_count = 0;                     // reset for next graph replay
    }
}

extern "C" void kernel_launch(void* const* d_in, const int* in_sizes, int n_in,
                              void* d_out, int out_size)
{
    const float* label = (const float*)d_in[0];
    const float* est   = (const float*)d_in[1];
    const int*   mix   = (const int*)d_in[2];
    int B = in_sizes[2];  // mix_way element count

    fused_kernel<<<NBLK, NTHR>>>(label, est, mix, (float*)d_out, B);
}

// round 10
// speedup vs baseline: 1.1416x; 1.1129x over previous
#include <cuda_runtime.h>
#include <cuda_bf16.h>

// ---------------------------------------------------------------------------
// label_loss: B=4.19M elements -> 3 scalars. Memory-bound (218 MB read).
// R10: R6 champion (2 elem/thread float4, 6 CTAs/SM, 888 blocks, 41.5us)
// + warp-wide prefetch.global.L2 of the NEXT grid-stride iteration.
// Evidence: occ 70%->97% (R9) left DRAM flat at ~5.3-5.5 TB/s => limit is
// demand-generation starvation (warps batch 7 LDGs then stall ~600cyc),
// not warp count. Prefetch issues next iter's 26 lines with one reg-free
// instruction per warp-iter, keeping DRAM fed during compute.
// ---------------------------------------------------------------------------

#define NBLK 888        // 148 SMs * 6 CTAs -> one wave
#define NTHR 256

static __device__ float g_part[5][NBLK];   // SoA: coalesced finalize reads
static __device__ int   g_count = 0;       // reset by the finalizing block

__device__ __forceinline__ float4 ldcs4(const float4* p) {
    float4 v;
    asm volatile("ld.global.cs.v4.f32 {%0,%1,%2,%3}, [%4];"
                 : "=f"(v.x), "=f"(v.y), "=f"(v.z), "=f"(v.w) : "l"(p));
    return v;
}

__device__ __forceinline__ int2 ldcs2i(const int2* p) {
    int2 v;
    asm volatile("ld.global.cs.v2.s32 {%0,%1}, [%2];"
                 : "=r"(v.x), "=r"(v.y) : "l"(p));
    return v;
}

__device__ __forceinline__ float angdiff_deg(float x1, float y1, float x2, float y2) {
    // |atan2(y1,x1) - atan2(y2,x2)| wrapped to [0, 180], in degrees.
    float cr = fmaf(y1, x2, -x1 * y2);
    float dt = fmaf(x1, x2,  y1 * y2);
    float p  = fabsf(cr);
    float q  = fabsf(dt);
    float mx = fmaxf(fmaxf(p, q), 1e-38f);
    float mn = fminf(p, q);
    float r  = __fdividef(mn, mx);       // r in [0, 1]
    float t2 = r * r;
    const float D = 57.29577951308232f;  // rad -> deg folded into coefficients
    float pl;
    pl = fmaf(t2, -0.01172120f * D,  0.05265332f * D);
    pl = fmaf(t2, pl,           -0.11643287f * D);
    pl = fmaf(t2, pl,            0.19354346f * D);
    pl = fmaf(t2, pl,           -0.33262347f * D);
    pl = fmaf(t2, pl,            0.99997726f * D);
    float at = r * pl;                   // atan(mn/mx) in degrees, [0, 45]
    float a  = (p > q)      ? (90.0f  - at) : at;
    a        = (dt < 0.0f)  ? (180.0f - a ) : a;
    return a;
}

struct Acc { float S, M, A1, A2; };

__device__ __forceinline__ void proc(
    float l00, float l01, float l10, float l11, float l20, float l21,
    float e0, float e1, float e2, float e3, float e4, float e5,
    int m, Acc& a)
{
    float d0 = e0 - l00, d1 = e1 - l10, d2 = e2 - l20;
    float s11 = fmaf(d2, d2, fmaf(d1, d1, d0 * d0));
    float f0 = e3 - l01, f1 = e4 - l11, f2 = e5 - l21;
    float s22 = fmaf(f2, f2, fmaf(f1, f1, f0 * f0));
    float g0 = e0 - l01, g1 = e1 - l11, g2 = e2 - l21;
    float s12 = fmaf(g2, g2, fmaf(g1, g1, g0 * g0));
    float h0 = e3 - l00, h1 = e4 - l10, h2 = e5 - l20;
    float s21 = fmaf(h2, h2, fmaf(h1, h1, h0 * h0));

    a.S += s11;
    float mixed = fminf(s11 + s22, s12 + s21);  // /3 deferred to finalize
    a.M  += (m != 0) ? mixed : 0.0f;

    float a11 = angdiff_deg(l00, l10, e0, e1);
    float a22 = angdiff_deg(l01, l11, e3, e4);
    float a12 = angdiff_deg(l00, l10, e3, e4);
    float a21 = angdiff_deg(l01, l11, e0, e1);
    bool ud = (a11 + a22) < (a12 + a21);
    a.A1 += ud ? a11 : a12;
    a.A2 += ud ? a22 : a21;
}

__global__ void __launch_bounds__(NTHR, 6)
fused_kernel(const float* __restrict__ label, const float* __restrict__ est,
             const int* __restrict__ mix, float* __restrict__ out, int B)
{
    Acc a{0.f, 0.f, 0.f, 0.f};
    int c0 = 0;
    const float4* L4 = (const float4*)label;
    const float4* E4 = (const float4*)est;
    const int2*   M2 = (const int2*)mix;
    int np = B >> 1;  // pairs; 2 elements = 3 float4 per array
    const int lane = threadIdx.x & 31;

    for (int pi = blockIdx.x * NTHR + threadIdx.x; pi < np; pi += NBLK * NTHR) {
        // ---- warp-wide L2 prefetch of NEXT iteration's window ----
        // Next-iter warp base pair: this warp covers pairs [wb, wb+32);
        // label/est bytes per warp-iter = 32*48 = 1536B = 12 lines each,
        // mix = 32*8 = 256B = 2 lines. Lane l covers one 128B line.
        {
            int wbn = (pi - lane) + NBLK * NTHR;      // next iter's warp base
            if (wbn + 32 <= np) {
                const char* pf;
                size_t o48 = (size_t)wbn * 48;
                if (lane < 12)      pf = (const char*)label + o48 + (size_t)lane * 128;
                else if (lane < 24) pf = (const char*)est   + o48 + (size_t)(lane - 12) * 128;
                else                pf = (const char*)mix   + (size_t)wbn * 8
                                          + (size_t)(lane - 24) * 128;
                if (lane < 26)
                    asm volatile("prefetch.global.L2 [%0];" :: "l"(pf));
            }
        }

        float4 La = ldcs4(&L4[3 * pi + 0]);
        float4 Lb = ldcs4(&L4[3 * pi + 1]);
        float4 Lc = ldcs4(&L4[3 * pi + 2]);
        float4 Ea = ldcs4(&E4[3 * pi + 0]);
        float4 Eb = ldcs4(&E4[3 * pi + 1]);
        float4 Ec = ldcs4(&E4[3 * pi + 2]);
        int2 mw = ldcs2i(&M2[pi]);
        proc(La.x, La.y, La.z, La.w, Lb.x, Lb.y,
             Ea.x, Ea.y, Ea.z, Ea.w, Eb.x, Eb.y, mw.x, a);
        proc(Lb.z, Lb.w, Lc.x, Lc.y, Lc.z, Lc.w,
             Eb.z, Eb.w, Ec.x, Ec.y, Ec.z, Ec.w, mw.y, a);
        c0 += (mw.x == 0) + (mw.y == 0);
    }
    // Odd-B tail (not hit for B=4194304, kept for generality)
    if ((B & 1) && blockIdx.x == 0 && threadIdx.x == 0) {
        int i = B - 1;
        const float* L = label + 6 * i;
        const float* E = est   + 6 * i;
        int m = mix[i];
        proc(L[0], L[1], L[2], L[3], L[4], L[5],
             E[0], E[1], E[2], E[3], E[4], E[5], m, a);
        c0 += (m == 0);
    }

    // Deterministic block reduction -> per-block float partials.
    float v[5] = {a.S, a.M, a.A1, a.A2, (float)c0};
    __shared__ float sh[5][NTHR / 32];
    #pragma unroll
    for (int k = 0; k < 5; k++) {
        float x = v[k];
        #pragma unroll
        for (int o = 16; o; o >>= 1) x += __shfl_down_sync(0xffffffffu, x, o);
        if ((threadIdx.x & 31) == 0) sh[k][threadIdx.x >> 5] = x;
    }
    __syncthreads();
    if (threadIdx.x < 5) {
        float s = 0.f;
        #pragma unroll
        for (int j = 0; j < NTHR / 32; j++) s += sh[threadIdx.x][j];
        g_part[threadIdx.x][blockIdx.x] = s;
    }

    // ---- last-block-done finalize (deterministic fixed-order re-reduce) ----
    __shared__ int is_last;
    __threadfence();                     // publish g_part before the count
    if (threadIdx.x == 0) {
        int prev = atomicAdd(&g_count, 1);
        is_last = (prev == NBLK - 1);
    }
    __syncthreads();
    if (!is_last) return;
    __threadfence();                     // acquire all blocks' g_part

    // Float accumulation (tree-structured; rel err ~1e-6, tol is 1e-3).
    float v5[5] = {0.f, 0.f, 0.f, 0.f, 0.f};
    for (int i = threadIdx.x; i < NBLK; i += NTHR) {
        #pragma unroll
        for (int k = 0; k < 5; k++) v5[k] += g_part[k][i];
    }
    __shared__ float shf[5][NTHR / 32];
    #pragma unroll
    for (int k = 0; k < 5; k++) {
        float x = v5[k];
        #pragma unroll
        for (int o = 16; o; o >>= 1) x += __shfl_down_sync(0xffffffffu, x, o);
        if ((threadIdx.x & 31) == 0) shf[k][threadIdx.x >> 5] = x;
    }
    __syncthreads();
    if (threadIdx.x == 0) {
        double t[5];
        #pragma unroll
        for (int k = 0; k < 5; k++) {
            float s = 0.f;
            #pragma unroll
            for (int j = 0; j < NTHR / 32; j++) s += shf[k][j];
            t[k] = (double)s;
        }
        double Bn = (double)B;
        double single = t[0] / (3.0 * Bn);                   // S / (3B)
        out[0] = (float)((t[4] * single + t[1] / 3.0) / Bn); // label_loss
        out[1] = (float)(t[2] / Bn);                         // mae1
        out[2] = (float)(t[3] / Bn);                         // mae2
        g_count = 0;                     // reset for next graph replay
    }
}

extern "C" void kernel_launch(void* const* d_in, const int* in_sizes, int n_in,
                              void* d_out, int out_size)
{
    const float* label = (const float*)d_in[0];
    const float* est   = (const float*)d_in[1];
    const int*   mix   = (const int*)d_in[2];
    int B = in_sizes[2];  // mix_way element count

    fused_kernel<<<NBLK, NTHR>>>(label, est, mix, (float*)d_out, B);
}